// round 10
// baseline (speedup 1.0000x reference)
#include <cuda_runtime.h>
#include <cuda_fp16.h>
#include <cstdint>

#define B_ 16
#define T_ 256
#define IN_ 512
#define H_ 1024
#define G_ 4096
#define NL_ 8
#define BT_ 4096
#define NCTA 64

// scan smem: sRed [8][16][72]f + sC 256f + sA 16x1048h
#define SMEM_SCAN (8*16*72*4 + 256*4 + 16*1048*2)
// proj smem: double-buffered A,B tiles 128x(64+8) halves each
#define PSTRIDE 72
#define SMEM_PROJ (4 * 128 * PSTRIDE * 2)

// ---------------- device scratch (allocation-free) ----------------
__device__ __half g_Xh[(size_t)BT_ * IN_];
__device__ __half g_Wih0[(size_t)G_ * IN_];
__device__ __half g_WihR[(size_t)(NL_ - 1) * G_ * H_];
__device__ __half g_Whh[(size_t)NL_ * G_ * H_];
__device__ float  g_XG[(size_t)T_ * B_ * G_];   // [t][b][gate*1024+hu]
__device__ __half g_Xb0[(size_t)BT_ * H_];
__device__ __half g_Xb1[(size_t)BT_ * H_];
__device__ __half g_hbuf[2 * B_ * H_];
__device__ int    g_ctr[NL_ * T_];
__device__ float  g_finh[B_ * H_];
__device__ float  g_fc1o[B_ * 512];
__device__ float  g_fc2o[B_ * 256];

// ---------------- helpers ----------------
__device__ __forceinline__ void mma16816(float* d, const uint32_t* a, uint32_t b0, uint32_t b1) {
    asm volatile("mma.sync.aligned.m16n8k16.row.col.f32.f16.f16.f32 "
                 "{%0,%1,%2,%3}, {%4,%5,%6,%7}, {%8,%9}, {%0,%1,%2,%3};"
                 : "+f"(d[0]), "+f"(d[1]), "+f"(d[2]), "+f"(d[3])
                 : "r"(a[0]), "r"(a[1]), "r"(a[2]), "r"(a[3]), "r"(b0), "r"(b1));
}
__device__ __forceinline__ int ldacq(const int* p) {
    int v; asm volatile("ld.acquire.gpu.global.b32 %0, [%1];" : "=r"(v) : "l"(p) : "memory");
    return v;
}
__device__ __forceinline__ void addRel(int* p) {
    asm volatile("red.release.gpu.global.add.s32 [%0], %1;" :: "l"(p), "r"(1) : "memory");
}
__device__ __forceinline__ uint4 ldcg16(const void* p) {
    uint4 v;
    asm volatile("ld.global.cg.v4.u32 {%0,%1,%2,%3}, [%4];"
                 : "=r"(v.x), "=r"(v.y), "=r"(v.z), "=r"(v.w) : "l"(p));
    return v;
}
__device__ __forceinline__ void cpa16(void* smem_dst, const void* gsrc) {
    uint32_t s = (uint32_t)__cvta_generic_to_shared(smem_dst);
    asm volatile("cp.async.cg.shared.global [%0], [%1], 16;" :: "r"(s), "l"(gsrc));
}
__device__ __forceinline__ uint32_t smaddr(const void* p) {
    return (uint32_t)__cvta_generic_to_shared(const_cast<void*>(p));
}
__device__ __forceinline__ void ldsm4(uint32_t* r, uint32_t a) {
    asm volatile("ldmatrix.sync.aligned.m8n8.x4.shared.b16 {%0,%1,%2,%3}, [%4];"
                 : "=r"(r[0]), "=r"(r[1]), "=r"(r[2]), "=r"(r[3]) : "r"(a));
}
__device__ __forceinline__ float sigf(float x) { return 1.f / (1.f + __expf(-x)); }
__device__ __forceinline__ float tanhfast(float x) { return 2.f * sigf(2.f * x) - 1.f; }

// ---------------- utility kernels ----------------
__global__ void __launch_bounds__(256) k_f2h(const float* __restrict__ s, int dsel, size_t n) {
    __half* d = dsel == 0 ? g_Xh : dsel == 1 ? g_Wih0 : dsel == 2 ? g_WihR : g_Whh;
    size_t i = blockIdx.x * (size_t)blockDim.x + threadIdx.x;
    size_t st = (size_t)gridDim.x * blockDim.x;
    for (size_t k = i * 4; k < n; k += st * 4) {
        float4 v = *(const float4*)(s + k);
        __half2* o = (__half2*)(d + k);
        o[0] = __floats2half2_rn(v.x, v.y);
        o[1] = __floats2half2_rn(v.z, v.w);
    }
}
__global__ void __launch_bounds__(256) k_zero() {
    int i = blockIdx.x * blockDim.x + threadIdx.x;
    if (i < NL_ * T_) g_ctr[i] = 0;
}

// ---------------- input projection GEMM ----------------
// 128x128 tile, BK=64, cp.async double-buffered, ldmatrix fragments.
// C[row=b*T+t][j] = A[row]·W[j] + bih[j] + bhh[j] -> XG[t][b][j]
__global__ void __launch_bounds__(256) k_proj(int l, const float* __restrict__ bih,
                                              const float* __restrict__ bhh) {
    extern __shared__ __half psm[];
    __half* sA = psm;                       // [2][128*72]
    __half* sB = psm + 2 * 128 * PSTRIDE;   // [2][128*72]
    int K = l ? H_ : IN_;
    const __half* Ag = (l == 0) ? g_Xh : ((l & 1) ? g_Xb0 : g_Xb1);
    const __half* Wg = l ? (g_WihR + (size_t)(l - 1) * G_ * H_) : g_Wih0;
    int tid = threadIdx.x, lane = tid & 31, w = tid >> 5;
    int wm = w >> 1, wn = w & 1, q = lane >> 2, r4 = lane & 3;
    int bM = blockIdx.y, bN = blockIdx.x;

    int lrow[4], lch[4];
#pragma unroll
    for (int p = 0; p < 4; p++) { int id = p * 256 + tid; lrow[p] = id >> 3; lch[p] = (id & 7) * 8; }

    // ldmatrix lane offsets (in halves, relative to tile base)
    int aOff = (wm * 32 + (lane & 15)) * PSTRIDE + ((lane >> 4) << 3);
    int bOff = (wn * 64 + ((lane >> 4) << 3) + (lane & 7)) * PSTRIDE + (((lane >> 3) & 1) << 3);

    float acc[2][8][4];
#pragma unroll
    for (int a = 0; a < 2; a++)
        for (int b = 0; b < 8; b++)
            for (int r = 0; r < 4; r++) acc[a][b][r] = 0.f;

#pragma unroll
    for (int p = 0; p < 4; p++) {
        cpa16(sA + lrow[p] * PSTRIDE + lch[p], Ag + (size_t)(bM * 128 + lrow[p]) * K + lch[p]);
        cpa16(sB + lrow[p] * PSTRIDE + lch[p], Wg + (size_t)(bN * 128 + lrow[p]) * K + lch[p]);
    }
    asm volatile("cp.async.commit_group;");

    int buf = 0;
    for (int kt = 0; kt < K; kt += 64, buf ^= 1) {
        bool more = (kt + 64) < K;
        if (more) {
            __half* dA = sA + (buf ^ 1) * 128 * PSTRIDE;
            __half* dB = sB + (buf ^ 1) * 128 * PSTRIDE;
#pragma unroll
            for (int p = 0; p < 4; p++) {
                cpa16(dA + lrow[p] * PSTRIDE + lch[p], Ag + (size_t)(bM * 128 + lrow[p]) * K + kt + 64 + lch[p]);
                cpa16(dB + lrow[p] * PSTRIDE + lch[p], Wg + (size_t)(bN * 128 + lrow[p]) * K + kt + 64 + lch[p]);
            }
            asm volatile("cp.async.commit_group;");
            asm volatile("cp.async.wait_group 1;");
        } else {
            asm volatile("cp.async.wait_group 0;");
        }
        __syncthreads();
        uint32_t aAddr = smaddr(sA + buf * 128 * PSTRIDE + aOff);
        uint32_t bAddr = smaddr(sB + buf * 128 * PSTRIDE + bOff);
#pragma unroll
        for (int ks = 0; ks < 4; ks++) {
            uint32_t af[2][4], bf[4][4];
            ldsm4(af[0], aAddr + ks * 32);
            ldsm4(af[1], aAddr + 16 * PSTRIDE * 2 + ks * 32);
#pragma unroll
            for (int p = 0; p < 4; p++)
                ldsm4(bf[p], bAddr + p * 16 * PSTRIDE * 2 + ks * 32);
#pragma unroll
            for (int mt = 0; mt < 2; mt++)
#pragma unroll
                for (int nt = 0; nt < 8; nt++)
                    mma16816(acc[mt][nt], af[mt],
                             bf[nt >> 1][(nt & 1) * 2], bf[nt >> 1][(nt & 1) * 2 + 1]);
        }
        __syncthreads();
    }
    float bj[8][2];
#pragma unroll
    for (int nt = 0; nt < 8; nt++)
#pragma unroll
        for (int e = 0; e < 2; e++) {
            int j = bN * 128 + wn * 64 + nt * 8 + r4 * 2 + e;
            bj[nt][e] = bih[j] + bhh[j];
        }
#pragma unroll
    for (int mt = 0; mt < 2; mt++)
#pragma unroll
        for (int nt = 0; nt < 8; nt++)
#pragma unroll
            for (int r = 0; r < 4; r++) {
                int row = bM * 128 + wm * 32 + mt * 16 + q + ((r >> 1) << 3);
                int j = bN * 128 + wn * 64 + nt * 8 + r4 * 2 + (r & 1);
                int b = row >> 8, t = row & 255;
                g_XG[((size_t)t * B_ + b) * G_ + j] = acc[mt][nt][r] + bj[nt][r & 1];
            }
}

// ---------------- persistent recurrent scan (one layer) ----------------
// 64 CTAs; CTA cid owns hidden units [cid*16, cid*16+16) = 64 gate rows
// (local row lr = gate*16 + unit). 8-way K-split; weights stationary in
// registers (breg[8][8][2]); A (h) via ldmatrix; epilogue uses all 256 threads.
__global__ void __launch_bounds__(256, 1) k_scan(int l) {
    extern __shared__ unsigned char smem[];
    float* sRed = (float*)smem;                 // [8][16][72]
    float* sC = sRed + 8 * 16 * 72;             // 256 f
    __half* sA = (__half*)(sC + 256);           // 16 x 1048
    int tid = threadIdx.x, cid = blockIdx.x;
    int lane = tid & 31, w = tid >> 5;
    int q = lane >> 2, r4 = lane & 3;
    const __half* Wl = g_Whh + (size_t)l * G_ * H_;
    __half* Xnext = (l & 1) ? g_Xb1 : g_Xb0;

    // stationary weights -> registers, mma B-fragment layout
    // breg[nt][kk]: local rows lr = nt*8+q, gate = lr>>4, unit = lr&15
    uint32_t breg[8][8][2];
    {
        int kb = w * 128 + 2 * r4;
#pragma unroll
        for (int nt = 0; nt < 8; nt++) {
            int lr = nt * 8 + q;
            int grow = (lr >> 4) * H_ + cid * 16 + (lr & 15);
            const __half* rowp = Wl + (size_t)grow * H_ + kb;
#pragma unroll
            for (int kk = 0; kk < 8; kk++) {
                breg[nt][kk][0] = *(const uint32_t*)(rowp + kk * 16);
                breg[nt][kk][1] = *(const uint32_t*)(rowp + kk * 16 + 8);
            }
        }
    }
    sC[tid] = 0.f;
    int* ctr = g_ctr + l * T_;
    int eb = tid >> 4, eu = tid & 15, ehu = cid * 16 + eu;
    uint32_t lds_base = smaddr(sA + (lane & 15) * 1048 + w * 128 + ((lane >> 4) << 3));

    for (int t = 0; t < T_; t++) {
        int rp = t & 1;
        // prefetch gate pre-activations (latency hidden under h-load + mma)
        size_t xb = ((size_t)t * B_ + eb) * G_ + ehu;
        float xgi = g_XG[xb];
        float xgf = g_XG[xb + 1024];
        float xgg = g_XG[xb + 2048];
        float xgo = g_XG[xb + 3072];
        // broadcast h into sA
        if (t == 0) {
#pragma unroll
            for (int u = tid; u < 2048; u += 256) {
                int b = u >> 7, col = (u & 127) * 8;
                *(uint4*)(sA + b * 1048 + col) = make_uint4(0, 0, 0, 0);
            }
        } else {
            const __half* hsrc = g_hbuf + rp * B_ * H_;
#pragma unroll
            for (int u = tid; u < 2048; u += 256) {
                int b = u >> 7, col = (u & 127) * 8;
                uint4 v = ldcg16(hsrc + b * H_ + col);
                *(uint4*)(sA + b * 1048 + col) = v;
            }
        }
        __syncthreads();
        float acc[8][4];
#pragma unroll
        for (int i = 0; i < 8; i++)
            for (int j = 0; j < 4; j++) acc[i][j] = 0.f;
#pragma unroll
        for (int kk = 0; kk < 8; kk++) {
            uint32_t a[4];
            ldsm4(a, lds_base + kk * 32);
#pragma unroll
            for (int nt = 0; nt < 8; nt++)
                mma16816(acc[nt], a, breg[nt][kk][0], breg[nt][kk][1]);
        }
#pragma unroll
        for (int nt = 0; nt < 8; nt++)
#pragma unroll
            for (int r = 0; r < 4; r++) {
                int m = q + ((r >> 1) << 3);
                int col = nt * 8 + r4 * 2 + (r & 1);
                sRed[(w * 16 + m) * 72 + col] = acc[nt][r];
            }
        __syncthreads();
        {
            float gi0 = xgi, gf0 = xgf, gg0 = xgg, go0 = xgo;
            float gi1 = 0.f, gf1 = 0.f, gg1 = 0.f, go1 = 0.f;
#pragma unroll
            for (int ww = 0; ww < 8; ww += 2) {
                int b0 = (ww * 16 + eb) * 72, b1 = ((ww + 1) * 16 + eb) * 72;
                gi0 += sRed[b0 + eu];      gi1 += sRed[b1 + eu];
                gf0 += sRed[b0 + 16 + eu]; gf1 += sRed[b1 + 16 + eu];
                gg0 += sRed[b0 + 32 + eu]; gg1 += sRed[b1 + 32 + eu];
                go0 += sRed[b0 + 48 + eu]; go1 += sRed[b1 + 48 + eu];
            }
            float c = sC[tid];
            c = sigf(gf0 + gf1) * c + sigf(gi0 + gi1) * tanhfast(gg0 + gg1);
            float h = sigf(go0 + go1) * tanhfast(c);
            sC[tid] = c;
            __half hh = __float2half(h);
            g_hbuf[(1 - rp) * B_ * H_ + eb * H_ + ehu] = hh;
            Xnext[((size_t)eb * T_ + t) * H_ + ehu] = hh;
            if (l == NL_ - 1 && t == T_ - 1) g_finh[eb * H_ + ehu] = h;
        }
        __syncthreads();               // orders all stores before thread0's release
        if (tid == 0) {
            addRel(&ctr[t]);
            while (ldacq(&ctr[t]) < NCTA) {}
        }
        __syncthreads();
    }
}

// ---------------- FC head ----------------
__global__ void __launch_bounds__(256) k_fc(int isel, int osel, const float* __restrict__ wg,
                                            const float* __restrict__ bias, float* dext,
                                            int INn, int OUTn, int dorelu) {
    const float* in = isel == 0 ? g_finh : (isel == 1 ? g_fc1o : g_fc2o);
    float* out = osel == 3 ? dext : (osel == 1 ? g_fc1o : g_fc2o);
    int o = blockIdx.x * blockDim.x + threadIdx.x;
    if (o >= B_ * OUTn) return;
    int b = o / OUTn, j = o % OUTn;
    const float* ip = in + (size_t)b * INn;
    const float* wp = wg + (size_t)j * INn;
    float s = bias[j];
    for (int k = 0; k < INn; k += 4) {
        float4 a = *(const float4*)(ip + k);
        float4 v = *(const float4*)(wp + k);
        s += a.x * v.x + a.y * v.y + a.z * v.z + a.w * v.w;
    }
    if (dorelu) s = fmaxf(s, 0.f);
    out[b * OUTn + j] = s;
}

// ---------------- launch ----------------
extern "C" void kernel_launch(void* const* d_in, const int* in_sizes, int n_in,
                              void* d_out, int out_size) {
    const float* x    = (const float*)d_in[0];
    const float* Wih0 = (const float*)d_in[1];
    const float* WihR = (const float*)d_in[2];
    const float* Whh  = (const float*)d_in[3];
    const float* bih  = (const float*)d_in[4];
    const float* bhh  = (const float*)d_in[5];
    const float* f1w  = (const float*)d_in[6];
    const float* f1b  = (const float*)d_in[7];
    const float* f2w  = (const float*)d_in[8];
    const float* f2b  = (const float*)d_in[9];
    const float* f3w  = (const float*)d_in[10];
    const float* f3b  = (const float*)d_in[11];

    static int attr_set = 0;
    if (!attr_set) {
        cudaFuncSetAttribute(k_scan, cudaFuncAttributeMaxDynamicSharedMemorySize, SMEM_SCAN);
        cudaFuncSetAttribute(k_proj, cudaFuncAttributeMaxDynamicSharedMemorySize, SMEM_PROJ);
        attr_set = 1;
    }

    k_f2h<<<2048, 256>>>(x,    0, (size_t)BT_ * IN_);
    k_f2h<<<2048, 256>>>(Wih0, 1, (size_t)G_ * IN_);
    k_f2h<<<2048, 256>>>(WihR, 2, (size_t)(NL_ - 1) * G_ * H_);
    k_f2h<<<2048, 256>>>(Whh,  3, (size_t)NL_ * G_ * H_);
    k_zero<<<8, 256>>>();

    dim3 pg(32, 32);
    for (int l = 0; l < NL_; l++) {
        k_proj<<<pg, 256, SMEM_PROJ>>>(l, bih + l * G_, bhh + l * G_);
        k_scan<<<NCTA, 256, SMEM_SCAN>>>(l);
    }
    k_fc<<<32, 256>>>(0, 1, f1w, f1b, nullptr, 1024, 512, 1);
    k_fc<<<16, 256>>>(1, 2, f2w, f2b, nullptr, 512, 256, 1);
    k_fc<<<1, 32>>>(2, 3, f3w, f3b, (float*)d_out, 256, 1, 0);
}

// round 11
// speedup vs baseline: 1.1531x; 1.1531x over previous
#include <cuda_runtime.h>
#include <cuda_fp16.h>
#include <cstdint>

#define B_ 16
#define T_ 256
#define IN_ 512
#define H_ 1024
#define G_ 4096
#define NL_ 8
#define BT_ 4096
#define NCTA 128

// scan smem: sRed [8][16][40]f + sC 128f + sA 16x1048h
#define SMEM_SCAN (8*16*40*4 + 128*4 + 16*1048*2)
// proj smem: double-buffered A,B tiles 128x(64+8) halves each
#define PSTRIDE 72
#define SMEM_PROJ (4 * 128 * PSTRIDE * 2)

// ---------------- device scratch (allocation-free) ----------------
__device__ __half g_Xh[(size_t)BT_ * IN_];
__device__ __half g_Wih0[(size_t)G_ * IN_];
__device__ __half g_WihR[(size_t)(NL_ - 1) * G_ * H_];
__device__ __half g_Whh[(size_t)NL_ * G_ * H_];
__device__ float  g_XG[(size_t)T_ * B_ * G_];   // [t][b][gate*1024+hu]
__device__ __half g_Xb0[(size_t)BT_ * H_];
__device__ __half g_Xb1[(size_t)BT_ * H_];
__device__ __half g_hbuf[2 * B_ * H_];
__device__ int    g_ctr[NL_ * T_];
__device__ float  g_finh[B_ * H_];
__device__ float  g_fc1o[B_ * 512];
__device__ float  g_fc2o[B_ * 256];

// ---------------- helpers ----------------
__device__ __forceinline__ void mma16816(float* d, const uint32_t* a, uint32_t b0, uint32_t b1) {
    asm volatile("mma.sync.aligned.m16n8k16.row.col.f32.f16.f16.f32 "
                 "{%0,%1,%2,%3}, {%4,%5,%6,%7}, {%8,%9}, {%0,%1,%2,%3};"
                 : "+f"(d[0]), "+f"(d[1]), "+f"(d[2]), "+f"(d[3])
                 : "r"(a[0]), "r"(a[1]), "r"(a[2]), "r"(a[3]), "r"(b0), "r"(b1));
}
__device__ __forceinline__ int ldacq(const int* p) {
    int v; asm volatile("ld.acquire.gpu.global.b32 %0, [%1];" : "=r"(v) : "l"(p) : "memory");
    return v;
}
__device__ __forceinline__ void addRel(int* p) {
    asm volatile("red.release.gpu.global.add.s32 [%0], %1;" :: "l"(p), "r"(1) : "memory");
}
__device__ __forceinline__ uint4 ldcg16(const void* p) {
    uint4 v;
    asm volatile("ld.global.cg.v4.u32 {%0,%1,%2,%3}, [%4];"
                 : "=r"(v.x), "=r"(v.y), "=r"(v.z), "=r"(v.w) : "l"(p));
    return v;
}
__device__ __forceinline__ void cpa16(void* smem_dst, const void* gsrc) {
    uint32_t s = (uint32_t)__cvta_generic_to_shared(smem_dst);
    asm volatile("cp.async.cg.shared.global [%0], [%1], 16;" :: "r"(s), "l"(gsrc));
}
__device__ __forceinline__ uint32_t smaddr(const void* p) {
    return (uint32_t)__cvta_generic_to_shared(const_cast<void*>(p));
}
__device__ __forceinline__ void ldsm4(uint32_t* r, uint32_t a) {
    asm volatile("ldmatrix.sync.aligned.m8n8.x4.shared.b16 {%0,%1,%2,%3}, [%4];"
                 : "=r"(r[0]), "=r"(r[1]), "=r"(r[2]), "=r"(r[3]) : "r"(a));
}
__device__ __forceinline__ float sigf(float x) { return 1.f / (1.f + __expf(-x)); }
__device__ __forceinline__ float tanhfast(float x) { return 2.f * sigf(2.f * x) - 1.f; }

// ---------------- utility kernels ----------------
__global__ void __launch_bounds__(256) k_f2h(const float* __restrict__ s, int dsel, size_t n) {
    __half* d = dsel == 0 ? g_Xh : dsel == 1 ? g_Wih0 : dsel == 2 ? g_WihR : g_Whh;
    size_t i = blockIdx.x * (size_t)blockDim.x + threadIdx.x;
    size_t st = (size_t)gridDim.x * blockDim.x;
    for (size_t k = i * 4; k < n; k += st * 4) {
        float4 v = *(const float4*)(s + k);
        __half2* o = (__half2*)(d + k);
        o[0] = __floats2half2_rn(v.x, v.y);
        o[1] = __floats2half2_rn(v.z, v.w);
    }
}
__global__ void __launch_bounds__(256) k_zero() {
    int i = blockIdx.x * blockDim.x + threadIdx.x;
    if (i < NL_ * T_) g_ctr[i] = 0;
}

// ---------------- input projection GEMM ----------------
// 128x128 tile, BK=64, cp.async double-buffered, ldmatrix fragments.
// 2 CTAs/SM via launch_bounds for latency hiding.
// C[row=b*T+t][j] = A[row]·W[j] + bih[j] + bhh[j] -> XG[t][b][j]
__global__ void __launch_bounds__(256, 2) k_proj(int l, const float* __restrict__ bih,
                                                 const float* __restrict__ bhh) {
    extern __shared__ __half psm[];
    __half* sA = psm;                       // [2][128*72]
    __half* sB = psm + 2 * 128 * PSTRIDE;   // [2][128*72]
    int K = l ? H_ : IN_;
    const __half* Ag = (l == 0) ? g_Xh : ((l & 1) ? g_Xb0 : g_Xb1);
    const __half* Wg = l ? (g_WihR + (size_t)(l - 1) * G_ * H_) : g_Wih0;
    int tid = threadIdx.x, lane = tid & 31, w = tid >> 5;
    int wm = w >> 1, wn = w & 1, q = lane >> 2, r4 = lane & 3;
    int bM = blockIdx.y, bN = blockIdx.x;

    int lrow[4], lch[4];
#pragma unroll
    for (int p = 0; p < 4; p++) { int id = p * 256 + tid; lrow[p] = id >> 3; lch[p] = (id & 7) * 8; }

    // ldmatrix lane offsets (in halves, relative to tile base)
    int aOff = (wm * 32 + (lane & 15)) * PSTRIDE + ((lane >> 4) << 3);
    int bOff = (wn * 64 + ((lane >> 4) << 3) + (lane & 7)) * PSTRIDE + (((lane >> 3) & 1) << 3);

    float acc[2][8][4];
#pragma unroll
    for (int a = 0; a < 2; a++)
        for (int b = 0; b < 8; b++)
            for (int r = 0; r < 4; r++) acc[a][b][r] = 0.f;

#pragma unroll
    for (int p = 0; p < 4; p++) {
        cpa16(sA + lrow[p] * PSTRIDE + lch[p], Ag + (size_t)(bM * 128 + lrow[p]) * K + lch[p]);
        cpa16(sB + lrow[p] * PSTRIDE + lch[p], Wg + (size_t)(bN * 128 + lrow[p]) * K + lch[p]);
    }
    asm volatile("cp.async.commit_group;");

    int buf = 0;
    for (int kt = 0; kt < K; kt += 64, buf ^= 1) {
        bool more = (kt + 64) < K;
        if (more) {
            __half* dA = sA + (buf ^ 1) * 128 * PSTRIDE;
            __half* dB = sB + (buf ^ 1) * 128 * PSTRIDE;
#pragma unroll
            for (int p = 0; p < 4; p++) {
                cpa16(dA + lrow[p] * PSTRIDE + lch[p], Ag + (size_t)(bM * 128 + lrow[p]) * K + kt + 64 + lch[p]);
                cpa16(dB + lrow[p] * PSTRIDE + lch[p], Wg + (size_t)(bN * 128 + lrow[p]) * K + kt + 64 + lch[p]);
            }
            asm volatile("cp.async.commit_group;");
            asm volatile("cp.async.wait_group 1;");
        } else {
            asm volatile("cp.async.wait_group 0;");
        }
        __syncthreads();
        uint32_t aAddr = smaddr(sA + buf * 128 * PSTRIDE + aOff);
        uint32_t bAddr = smaddr(sB + buf * 128 * PSTRIDE + bOff);
#pragma unroll
        for (int ks = 0; ks < 4; ks++) {
            uint32_t af[2][4], bf[4][4];
            ldsm4(af[0], aAddr + ks * 32);
            ldsm4(af[1], aAddr + 16 * PSTRIDE * 2 + ks * 32);
#pragma unroll
            for (int p = 0; p < 4; p++)
                ldsm4(bf[p], bAddr + p * 16 * PSTRIDE * 2 + ks * 32);
#pragma unroll
            for (int mt = 0; mt < 2; mt++)
#pragma unroll
                for (int nt = 0; nt < 8; nt++)
                    mma16816(acc[mt][nt], af[mt],
                             bf[nt >> 1][(nt & 1) * 2], bf[nt >> 1][(nt & 1) * 2 + 1]);
        }
        __syncthreads();
    }
    float bj[8][2];
#pragma unroll
    for (int nt = 0; nt < 8; nt++)
#pragma unroll
        for (int e = 0; e < 2; e++) {
            int j = bN * 128 + wn * 64 + nt * 8 + r4 * 2 + e;
            bj[nt][e] = bih[j] + bhh[j];
        }
#pragma unroll
    for (int mt = 0; mt < 2; mt++)
#pragma unroll
        for (int nt = 0; nt < 8; nt++)
#pragma unroll
            for (int r = 0; r < 4; r++) {
                int row = bM * 128 + wm * 32 + mt * 16 + q + ((r >> 1) << 3);
                int j = bN * 128 + wn * 64 + nt * 8 + r4 * 2 + (r & 1);
                int b = row >> 8, t = row & 255;
                g_XG[((size_t)t * B_ + b) * G_ + j] = acc[mt][nt][r] + bj[nt][r & 1];
            }
}

// ---------------- persistent recurrent scan (one layer) ----------------
// 128 CTAs; CTA cid owns hidden units [cid*8, cid*8+8) = 32 gate rows.
// 8-way K-split; weights stationary in registers; A via ldmatrix.
// (R9-proven structure.)
__global__ void __launch_bounds__(256, 1) k_scan(int l) {
    extern __shared__ unsigned char smem[];
    float* sRed = (float*)smem;                 // [8][16][40]
    float* sC = sRed + 8 * 16 * 40;             // 128 f
    __half* sA = (__half*)(sC + 128);           // 16 x 1048
    int tid = threadIdx.x, cid = blockIdx.x;
    int lane = tid & 31, w = tid >> 5;
    int q = lane >> 2, r4 = lane & 3;
    const __half* Wl = g_Whh + (size_t)l * G_ * H_;
    __half* Xnext = (l & 1) ? g_Xb1 : g_Xb0;

    // stationary weights -> registers, mma B-fragment layout
    uint32_t breg[4][8][2];
    {
        int kb = w * 128 + 2 * r4;
#pragma unroll
        for (int nt = 0; nt < 4; nt++) {
            const __half* rowp = Wl + (size_t)(nt * 1024 + cid * 8 + q) * H_ + kb;
#pragma unroll
            for (int kk = 0; kk < 8; kk++) {
                breg[nt][kk][0] = *(const uint32_t*)(rowp + kk * 16);
                breg[nt][kk][1] = *(const uint32_t*)(rowp + kk * 16 + 8);
            }
        }
    }
    if (tid < 128) sC[tid] = 0.f;
    int* ctr = g_ctr + l * T_;
    int eb = tid >> 3, ehl = tid & 7, ehu = cid * 8 + ehl;
    uint32_t lds_base = smaddr(sA + (lane & 15) * 1048 + w * 128 + ((lane >> 4) << 3));

    for (int t = 0; t < T_; t++) {
        int rp = t & 1;
        // prefetch gate pre-activations (latency hidden under h-load + mma)
        float xgi = 0.f, xgf = 0.f, xgg = 0.f, xgo = 0.f;
        if (tid < 128) {
            size_t xb = ((size_t)t * B_ + eb) * G_ + ehu;
            xgi = g_XG[xb];
            xgf = g_XG[xb + 1024];
            xgg = g_XG[xb + 2048];
            xgo = g_XG[xb + 3072];
        }
        // broadcast h into sA
        if (t == 0) {
#pragma unroll
            for (int u = tid; u < 2048; u += 256) {
                int b = u >> 7, col = (u & 127) * 8;
                *(uint4*)(sA + b * 1048 + col) = make_uint4(0, 0, 0, 0);
            }
        } else {
            const __half* hsrc = g_hbuf + rp * B_ * H_;
#pragma unroll
            for (int u = tid; u < 2048; u += 256) {
                int b = u >> 7, col = (u & 127) * 8;
                uint4 v = ldcg16(hsrc + b * H_ + col);
                *(uint4*)(sA + b * 1048 + col) = v;
            }
        }
        __syncthreads();
        float acc[4][4];
#pragma unroll
        for (int i = 0; i < 4; i++)
            for (int j = 0; j < 4; j++) acc[i][j] = 0.f;
#pragma unroll
        for (int kk = 0; kk < 8; kk++) {
            uint32_t a[4];
            ldsm4(a, lds_base + kk * 32);
#pragma unroll
            for (int nt = 0; nt < 4; nt++)
                mma16816(acc[nt], a, breg[nt][kk][0], breg[nt][kk][1]);
        }
#pragma unroll
        for (int nt = 0; nt < 4; nt++)
#pragma unroll
            for (int r = 0; r < 4; r++) {
                int m = q + ((r >> 1) << 3);
                int col = nt * 8 + r4 * 2 + (r & 1);
                sRed[(w * 16 + m) * 40 + col] = acc[nt][r];
            }
        __syncthreads();
        if (tid < 128) {
            float gi0 = xgi, gf0 = xgf, gg0 = xgg, go0 = xgo;
            float gi1 = 0.f, gf1 = 0.f, gg1 = 0.f, go1 = 0.f;
#pragma unroll
            for (int ww = 0; ww < 8; ww += 2) {
                int b0 = (ww * 16 + eb) * 40, b1 = ((ww + 1) * 16 + eb) * 40;
                gi0 += sRed[b0 + ehl];      gi1 += sRed[b1 + ehl];
                gf0 += sRed[b0 + 8 + ehl];  gf1 += sRed[b1 + 8 + ehl];
                gg0 += sRed[b0 + 16 + ehl]; gg1 += sRed[b1 + 16 + ehl];
                go0 += sRed[b0 + 24 + ehl]; go1 += sRed[b1 + 24 + ehl];
            }
            float c = sC[tid];
            c = sigf(gf0 + gf1) * c + sigf(gi0 + gi1) * tanhfast(gg0 + gg1);
            float h = sigf(go0 + go1) * tanhfast(c);
            sC[tid] = c;
            __half hh = __float2half(h);
            g_hbuf[(1 - rp) * B_ * H_ + eb * H_ + ehu] = hh;
            Xnext[((size_t)eb * T_ + t) * H_ + ehu] = hh;
            if (l == NL_ - 1 && t == T_ - 1) g_finh[eb * H_ + ehu] = h;
        }
        __syncthreads();               // orders all stores before thread0's release
        if (tid == 0) {
            addRel(&ctr[t]);
            while (ldacq(&ctr[t]) < NCTA) {}
        }
        __syncthreads();
    }
}

// ---------------- FC head ----------------
__global__ void __launch_bounds__(256) k_fc(int isel, int osel, const float* __restrict__ wg,
                                            const float* __restrict__ bias, float* dext,
                                            int INn, int OUTn, int dorelu) {
    const float* in = isel == 0 ? g_finh : (isel == 1 ? g_fc1o : g_fc2o);
    float* out = osel == 3 ? dext : (osel == 1 ? g_fc1o : g_fc2o);
    int o = blockIdx.x * blockDim.x + threadIdx.x;
    if (o >= B_ * OUTn) return;
    int b = o / OUTn, j = o % OUTn;
    const float* ip = in + (size_t)b * INn;
    const float* wp = wg + (size_t)j * INn;
    float s = bias[j];
    for (int k = 0; k < INn; k += 4) {
        float4 a = *(const float4*)(ip + k);
        float4 v = *(const float4*)(wp + k);
        s += a.x * v.x + a.y * v.y + a.z * v.z + a.w * v.w;
    }
    if (dorelu) s = fmaxf(s, 0.f);
    out[b * OUTn + j] = s;
}

// ---------------- launch ----------------
extern "C" void kernel_launch(void* const* d_in, const int* in_sizes, int n_in,
                              void* d_out, int out_size) {
    const float* x    = (const float*)d_in[0];
    const float* Wih0 = (const float*)d_in[1];
    const float* WihR = (const float*)d_in[2];
    const float* Whh  = (const float*)d_in[3];
    const float* bih  = (const float*)d_in[4];
    const float* bhh  = (const float*)d_in[5];
    const float* f1w  = (const float*)d_in[6];
    const float* f1b  = (const float*)d_in[7];
    const float* f2w  = (const float*)d_in[8];
    const float* f2b  = (const float*)d_in[9];
    const float* f3w  = (const float*)d_in[10];
    const float* f3b  = (const float*)d_in[11];

    static int attr_set = 0;
    if (!attr_set) {
        cudaFuncSetAttribute(k_scan, cudaFuncAttributeMaxDynamicSharedMemorySize, SMEM_SCAN);
        cudaFuncSetAttribute(k_proj, cudaFuncAttributeMaxDynamicSharedMemorySize, SMEM_PROJ);
        attr_set = 1;
    }

    k_f2h<<<2048, 256>>>(x,    0, (size_t)BT_ * IN_);
    k_f2h<<<2048, 256>>>(Wih0, 1, (size_t)G_ * IN_);
    k_f2h<<<2048, 256>>>(WihR, 2, (size_t)(NL_ - 1) * G_ * H_);
    k_f2h<<<2048, 256>>>(Whh,  3, (size_t)NL_ * G_ * H_);
    k_zero<<<8, 256>>>();

    dim3 pg(32, 32);
    for (int l = 0; l < NL_; l++) {
        k_proj<<<pg, 256, SMEM_PROJ>>>(l, bih + l * G_, bhh + l * G_);
        k_scan<<<NCTA, 256, SMEM_SCAN>>>(l);
    }
    k_fc<<<32, 256>>>(0, 1, f1w, f1b, nullptr, 1024, 512, 1);
    k_fc<<<16, 256>>>(1, 2, f2w, f2b, nullptr, 512, 256, 1);
    k_fc<<<1, 32>>>(2, 3, f3w, f3b, (float*)d_out, 256, 1, 0);
}